// round 2
// baseline (speedup 1.0000x reference)
#include <cuda_runtime.h>
#include <cuda_bf16.h>
#include <mma.h>

using namespace nvcuda;

#define N_TOK 4096
#define TOPK  64
#define DIM   1024
#define NLAT  16384

// ---------------- device scratch (statically allocated; no runtime allocs) ----
__device__ float g_colsum[DIM];
__device__ float g_sumy2;
__device__ float g_err2;
__device__ float g_sae_scratch[N_TOK * DIM];  // fallback if d_out can't hold sae_out

// ---------------- kernel 0: zero the reduction scratch ----------------------
__global__ void zero_kernel() {
    int t = blockIdx.x * blockDim.x + threadIdx.x;
    if (t < DIM) g_colsum[t] = 0.0f;
    if (t == 0) { g_sumy2 = 0.0f; g_err2 = 0.0f; }
}

// ---------------- kernel 1: y column sums + sum(y^2) -------------------------
// grid (DIM/256, 64), block 256. Each block: 256 columns x 64 rows.
__global__ __launch_bounds__(256) void ystats_kernel(const float* __restrict__ y) {
    int c  = blockIdx.x * 256 + threadIdx.x;
    int r0 = blockIdx.y * 64;
    float s = 0.0f, s2 = 0.0f;
#pragma unroll 4
    for (int r = 0; r < 64; r++) {
        float v = y[(r0 + r) * DIM + c];
        s += v;
        s2 += v * v;
    }
    atomicAdd(&g_colsum[c], s);
    __shared__ float red[256];
    red[threadIdx.x] = s2;
    __syncthreads();
    for (int off = 128; off > 0; off >>= 1) {
        if (threadIdx.x < off) red[threadIdx.x] += red[threadIdx.x + off];
        __syncthreads();
    }
    if (threadIdx.x == 0) atomicAdd(&g_sumy2, red[0]);
}

// ---------------- kernel 2: skip GEMM  out = x @ W_skip^T (tf32 wmma) --------
// out[n][d] = sum_j x[n][j] * W_skip[d][j]
#define BM 128
#define BN 64
#define BK 32
#define LDS 36  // padded leading dim (floats); 36*4B = 144B, 16B-aligned rows

__global__ __launch_bounds__(256) void skip_gemm_kernel(
    const float* __restrict__ x, const float* __restrict__ Wskip,
    float* __restrict__ out)
{
    __shared__ float As[BM * LDS];
    __shared__ float Bs[BN * LDS];
    const int m0 = blockIdx.y * BM;
    const int n0 = blockIdx.x * BN;
    const int warpId = threadIdx.x >> 5;
    const int wm = warpId >> 1;   // 0..3 (rows of 32)
    const int wn = warpId & 1;    // 0..1 (cols of 32)

    wmma::fragment<wmma::accumulator, 16, 16, 8, float> c[2][2];
#pragma unroll
    for (int i = 0; i < 2; i++)
#pragma unroll
        for (int j = 0; j < 2; j++) wmma::fill_fragment(c[i][j], 0.0f);

    for (int k0 = 0; k0 < DIM; k0 += BK) {
        // A tile: 128x32 floats -> 1024 float4 / 256 threads = 4 each
#pragma unroll
        for (int i = 0; i < 4; i++) {
            int idx = threadIdx.x + i * 256;
            int row = idx >> 3, kg = idx & 7;
            float4 v = *(const float4*)&x[(m0 + row) * DIM + k0 + kg * 4];
            *(float4*)&As[row * LDS + kg * 4] = v;
        }
        // B tile: 64x32 floats -> 512 float4 / 256 threads = 2 each
#pragma unroll
        for (int i = 0; i < 2; i++) {
            int idx = threadIdx.x + i * 256;
            int row = idx >> 3, kg = idx & 7;
            float4 v = *(const float4*)&Wskip[(n0 + row) * DIM + k0 + kg * 4];
            *(float4*)&Bs[row * LDS + kg * 4] = v;
        }
        __syncthreads();

#pragma unroll
        for (int kk = 0; kk < 4; kk++) {
            wmma::fragment<wmma::matrix_a, 16, 16, 8, wmma::precision::tf32, wmma::row_major> a[2];
            wmma::fragment<wmma::matrix_b, 16, 16, 8, wmma::precision::tf32, wmma::col_major> b[2];
#pragma unroll
            for (int i = 0; i < 2; i++) {
                wmma::load_matrix_sync(a[i], &As[(wm * 32 + i * 16) * LDS + kk * 8], LDS);
#pragma unroll
                for (int t = 0; t < a[i].num_elements; t++)
                    a[i].x[t] = wmma::__float_to_tf32(a[i].x[t]);
            }
#pragma unroll
            for (int j = 0; j < 2; j++) {
                // Bs is [n][k] row-major == [k][n] col-major with ld = LDS
                wmma::load_matrix_sync(b[j], &Bs[(wn * 32 + j * 16) * LDS + kk * 8], LDS);
#pragma unroll
                for (int t = 0; t < b[j].num_elements; t++)
                    b[j].x[t] = wmma::__float_to_tf32(b[j].x[t]);
            }
#pragma unroll
            for (int i = 0; i < 2; i++)
#pragma unroll
                for (int j = 0; j < 2; j++)
                    wmma::mma_sync(c[i][j], a[i], b[j], c[i][j]);
        }
        __syncthreads();
    }

#pragma unroll
    for (int i = 0; i < 2; i++)
#pragma unroll
        for (int j = 0; j < 2; j++) {
            int row = m0 + wm * 32 + i * 16;
            int col = n0 + wn * 32 + j * 16;
            wmma::store_matrix_sync(&out[(size_t)row * DIM + col], c[i][j], DIM,
                                    wmma::mem_row_major);
        }
}

// ---------------- kernel 3: decode gather + b_dec + e^2 ----------------------
// One CTA per token. Each thread owns 4 output dims (float4).
__global__ __launch_bounds__(256) void decode_kernel(
    const float* __restrict__ la, const int* __restrict__ li,
    const float* __restrict__ Wdec, const float* __restrict__ bdec,
    const float* __restrict__ penc, const float* __restrict__ pscale,
    const float* __restrict__ y, float* __restrict__ out)
{
    const int n = blockIdx.x;
    const int t = threadIdx.x;
    __shared__ int   s_idx[TOPK];
    __shared__ float s_act[TOPK];
    if (t < TOPK) {
        int l = li[n * TOPK + t];
        s_idx[t] = l;
        s_act[t] = (la[n * TOPK + t] + penc[l]) * pscale[l];
    }
    __syncthreads();

    const int c = t * 4;
    float4 acc = *(const float4*)&out[(size_t)n * DIM + c];  // skip-GEMM result
    const float4 bd = *(const float4*)&bdec[c];
    acc.x += bd.x; acc.y += bd.y; acc.z += bd.z; acc.w += bd.w;

#pragma unroll 4
    for (int k = 0; k < TOPK; k++) {
        const float a = s_act[k];
        const float4 w = *(const float4*)&Wdec[(size_t)s_idx[k] * DIM + c];
        acc.x += a * w.x; acc.y += a * w.y; acc.z += a * w.z; acc.w += a * w.w;
    }

    const float4 yv = *(const float4*)&y[(size_t)n * DIM + c];
    float ex = yv.x - acc.x, ey = yv.y - acc.y, ez = yv.z - acc.z, ew = yv.w - acc.w;
    float e2 = ex * ex + ey * ey + ez * ez + ew * ew;
    *(float4*)&out[(size_t)n * DIM + c] = acc;

    // warp reduce then cross-warp reduce
#pragma unroll
    for (int off = 16; off > 0; off >>= 1)
        e2 += __shfl_xor_sync(0xffffffffu, e2, off);
    __shared__ float wred[8];
    if ((t & 31) == 0) wred[t >> 5] = e2;
    __syncthreads();
    if (t < 8) {
        float v = wred[t];
#pragma unroll
        for (int off = 4; off > 0; off >>= 1)
            v += __shfl_xor_sync(0x000000ffu, v, off);
        if (t == 0) atomicAdd(&g_err2, v);
    }
}

// ---------------- kernel 4: finalize fvu -------------------------------------
__global__ void finalize_kernel(float* __restrict__ fvu_out) {
    __shared__ float red[1024];
    float s = g_colsum[threadIdx.x];
    red[threadIdx.x] = s * s;
    __syncthreads();
    for (int off = 512; off > 0; off >>= 1) {
        if (threadIdx.x < off) red[threadIdx.x] += red[threadIdx.x + off];
        __syncthreads();
    }
    if (threadIdx.x == 0) {
        float tv = g_sumy2 - red[0] / (float)N_TOK;
        *fvu_out = g_err2 / tv;
    }
}

// ---------------- launcher ----------------------------------------------------
extern "C" void kernel_launch(void* const* d_in, const int* in_sizes, int n_in,
                              void* d_out, int out_size)
{
    const float* x      = (const float*)d_in[0];
    const float* y      = (const float*)d_in[1];
    const float* la     = (const float*)d_in[2];
    const int*   li     = (const int*)  d_in[3];
    const float* Wdec   = (const float*)d_in[4];
    const float* bdec   = (const float*)d_in[5];
    const float* penc   = (const float*)d_in[6];
    const float* pscale = (const float*)d_in[7];
    const float* Wskip  = (const float*)d_in[8];

    float* outf = (float*)d_out;
    float* sae = outf;
    if (out_size < N_TOK * DIM) {
        void* p = nullptr;
        cudaGetSymbolAddress(&p, g_sae_scratch);
        sae = (float*)p;
    }
    float* fvu_ptr = outf + (out_size > 0 ? out_size - 1 : 0);

    zero_kernel<<<2, 512>>>();
    ystats_kernel<<<dim3(DIM / 256, 64), 256>>>(y);
    skip_gemm_kernel<<<dim3(DIM / BN, N_TOK / BM), 256>>>(x, Wskip, sae);
    decode_kernel<<<N_TOK, 256>>>(la, li, Wdec, bdec, penc, pscale, y, sae);
    finalize_kernel<<<1, 1024>>>(fvu_ptr);
}

// round 3
// speedup vs baseline: 1.0892x; 1.0892x over previous
#include <cuda_runtime.h>
#include <cuda_bf16.h>
#include <mma.h>

using namespace nvcuda;

#define N_TOK 4096
#define TOPK  64
#define DIM   1024
#define NLAT  16384

// ---------------- device scratch (statically allocated; no runtime allocs) ----
__device__ float g_colsum[DIM];
__device__ float g_sumy2;
__device__ float g_err2;
__device__ float g_sae_scratch[N_TOK * DIM];  // fallback if d_out can't hold sae_out

// ---------------- kernel 0: zero the reduction scratch ----------------------
__global__ void zero_kernel() {
    int t = blockIdx.x * blockDim.x + threadIdx.x;
    if (t < DIM) g_colsum[t] = 0.0f;
    if (t == 0) { g_sumy2 = 0.0f; g_err2 = 0.0f; }
}

// ---------------- kernel 1: y column sums + sum(y^2) -------------------------
__global__ __launch_bounds__(256) void ystats_kernel(const float* __restrict__ y) {
    int c  = blockIdx.x * 256 + threadIdx.x;
    int r0 = blockIdx.y * 64;
    float s = 0.0f, s2 = 0.0f;
#pragma unroll 4
    for (int r = 0; r < 64; r++) {
        float v = y[(r0 + r) * DIM + c];
        s += v;
        s2 += v * v;
    }
    atomicAdd(&g_colsum[c], s);
    __shared__ float red[256];
    red[threadIdx.x] = s2;
    __syncthreads();
    for (int off = 128; off > 0; off >>= 1) {
        if (threadIdx.x < off) red[threadIdx.x] += red[threadIdx.x + off];
        __syncthreads();
    }
    if (threadIdx.x == 0) atomicAdd(&g_sumy2, red[0]);
}

// ---------------- kernel 2: skip GEMM  out = x @ W_skip^T (tf32 wmma) --------
// 128x128 CTA tile, BK=32, cp.async double-buffered.
#define GM 128
#define GN 128
#define GK 32
#define GLD 36                       // padded row length in floats
#define ABUF (GM * GLD)              // one A buffer (floats)
#define BBUF (GN * GLD)              // one B buffer (floats)
#define GEMM_SMEM_BYTES ((2 * ABUF + 2 * BBUF) * 4)

__device__ __forceinline__ void cpa16(void* s, const void* g) {
    unsigned sa = (unsigned)__cvta_generic_to_shared(s);
    asm volatile("cp.async.cg.shared.global [%0], [%1], 16;" :: "r"(sa), "l"(g));
}

__global__ __launch_bounds__(256) void skip_gemm_kernel(
    const float* __restrict__ x, const float* __restrict__ Wskip,
    float* __restrict__ out)
{
    extern __shared__ float sm[];
    float* As = sm;               // [2][GM][GLD]
    float* Bs = sm + 2 * ABUF;    // [2][GN][GLD]

    const int m0 = blockIdx.y * GM;
    const int n0 = blockIdx.x * GN;
    const int tid = threadIdx.x;
    const int warp = tid >> 5;
    const int wm = warp & 3;      // 4 warp-rows of 32
    const int wn = warp >> 2;     // 2 warp-cols of 64

    wmma::fragment<wmma::accumulator, 16, 16, 8, float> c[2][4];
#pragma unroll
    for (int i = 0; i < 2; i++)
#pragma unroll
        for (int j = 0; j < 4; j++) wmma::fill_fragment(c[i][j], 0.0f);

    // per-thread load coordinates: 1024 float4 per tile / 256 threads = 4 each
    const int lrow = tid >> 3;        // base row 0..31 pattern repeated
    const int lkg  = (tid & 7) * 4;   // 0,4,..28

    auto issue = [&](int kt, int buf) {
        const int k0 = kt * GK;
        float* a = As + buf * ABUF;
        float* b = Bs + buf * BBUF;
#pragma unroll
        for (int i = 0; i < 4; i++) {
            int row = lrow + i * 32;
            cpa16(&a[row * GLD + lkg], &x[(size_t)(m0 + row) * DIM + k0 + lkg]);
        }
#pragma unroll
        for (int i = 0; i < 4; i++) {
            int row = lrow + i * 32;
            cpa16(&b[row * GLD + lkg], &Wskip[(size_t)(n0 + row) * DIM + k0 + lkg]);
        }
        asm volatile("cp.async.commit_group;");
    };

    const int NT = DIM / GK;  // 32
    issue(0, 0);

    for (int kt = 0; kt < NT; kt++) {
        const int buf = kt & 1;
        if (kt + 1 < NT) {
            issue(kt + 1, buf ^ 1);
            asm volatile("cp.async.wait_group 1;");
        } else {
            asm volatile("cp.async.wait_group 0;");
        }
        __syncthreads();

        const float* a_base = As + buf * ABUF + (wm * 32) * GLD;
        const float* b_base = Bs + buf * BBUF + (wn * 64) * GLD;
#pragma unroll
        for (int kk = 0; kk < 4; kk++) {
            wmma::fragment<wmma::matrix_a, 16, 16, 8, wmma::precision::tf32, wmma::row_major> af[2];
            wmma::fragment<wmma::matrix_b, 16, 16, 8, wmma::precision::tf32, wmma::col_major> bf[4];
#pragma unroll
            for (int i = 0; i < 2; i++) {
                wmma::load_matrix_sync(af[i], a_base + (i * 16) * GLD + kk * 8, GLD);
#pragma unroll
                for (int t = 0; t < af[i].num_elements; t++)
                    af[i].x[t] = wmma::__float_to_tf32(af[i].x[t]);
            }
#pragma unroll
            for (int j = 0; j < 4; j++) {
                wmma::load_matrix_sync(bf[j], b_base + (j * 16) * GLD + kk * 8, GLD);
#pragma unroll
                for (int t = 0; t < bf[j].num_elements; t++)
                    bf[j].x[t] = wmma::__float_to_tf32(bf[j].x[t]);
            }
#pragma unroll
            for (int i = 0; i < 2; i++)
#pragma unroll
                for (int j = 0; j < 4; j++)
                    wmma::mma_sync(c[i][j], af[i], bf[j], c[i][j]);
        }
        __syncthreads();
    }

#pragma unroll
    for (int i = 0; i < 2; i++)
#pragma unroll
        for (int j = 0; j < 4; j++) {
            int row = m0 + wm * 32 + i * 16;
            int col = n0 + wn * 64 + j * 16;
            wmma::store_matrix_sync(&out[(size_t)row * DIM + col], c[i][j], DIM,
                                    wmma::mem_row_major);
        }
}

// ---------------- kernel 3: decode gather + b_dec + e^2 ----------------------
__global__ __launch_bounds__(256) void decode_kernel(
    const float* __restrict__ la, const int* __restrict__ li,
    const float* __restrict__ Wdec, const float* __restrict__ bdec,
    const float* __restrict__ penc, const float* __restrict__ pscale,
    const float* __restrict__ y, float* __restrict__ out)
{
    const int n = blockIdx.x;
    const int t = threadIdx.x;
    __shared__ int   s_idx[TOPK];
    __shared__ float s_act[TOPK];
    if (t < TOPK) {
        int l = li[n * TOPK + t];
        s_idx[t] = l;
        s_act[t] = (la[n * TOPK + t] + penc[l]) * pscale[l];
    }
    __syncthreads();

    const int c = t * 4;
    float4 acc = *(const float4*)&out[(size_t)n * DIM + c];  // skip-GEMM result
    const float4 bd = *(const float4*)&bdec[c];
    acc.x += bd.x; acc.y += bd.y; acc.z += bd.z; acc.w += bd.w;

#pragma unroll 4
    for (int k = 0; k < TOPK; k++) {
        const float a = s_act[k];
        const float4 w = *(const float4*)&Wdec[(size_t)s_idx[k] * DIM + c];
        acc.x += a * w.x; acc.y += a * w.y; acc.z += a * w.z; acc.w += a * w.w;
    }

    const float4 yv = *(const float4*)&y[(size_t)n * DIM + c];
    float ex = yv.x - acc.x, ey = yv.y - acc.y, ez = yv.z - acc.z, ew = yv.w - acc.w;
    float e2 = ex * ex + ey * ey + ez * ez + ew * ew;
    *(float4*)&out[(size_t)n * DIM + c] = acc;

#pragma unroll
    for (int off = 16; off > 0; off >>= 1)
        e2 += __shfl_xor_sync(0xffffffffu, e2, off);
    __shared__ float wred[8];
    if ((t & 31) == 0) wred[t >> 5] = e2;
    __syncthreads();
    if (t < 8) {
        float v = wred[t];
#pragma unroll
        for (int off = 4; off > 0; off >>= 1)
            v += __shfl_xor_sync(0x000000ffu, v, off);
        if (t == 0) atomicAdd(&g_err2, v);
    }
}

// ---------------- kernel 4: finalize fvu -------------------------------------
__global__ void finalize_kernel(float* __restrict__ fvu_out) {
    __shared__ float red[1024];
    float s = g_colsum[threadIdx.x];
    red[threadIdx.x] = s * s;
    __syncthreads();
    for (int off = 512; off > 0; off >>= 1) {
        if (threadIdx.x < off) red[threadIdx.x] += red[threadIdx.x + off];
        __syncthreads();
    }
    if (threadIdx.x == 0) {
        float tv = g_sumy2 - red[0] / (float)N_TOK;
        *fvu_out = g_err2 / tv;
    }
}

// ---------------- launcher ----------------------------------------------------
extern "C" void kernel_launch(void* const* d_in, const int* in_sizes, int n_in,
                              void* d_out, int out_size)
{
    const float* x      = (const float*)d_in[0];
    const float* y      = (const float*)d_in[1];
    const float* la     = (const float*)d_in[2];
    const int*   li     = (const int*)  d_in[3];
    const float* Wdec   = (const float*)d_in[4];
    const float* bdec   = (const float*)d_in[5];
    const float* penc   = (const float*)d_in[6];
    const float* pscale = (const float*)d_in[7];
    const float* Wskip  = (const float*)d_in[8];

    float* outf = (float*)d_out;
    float* sae = outf;
    if (out_size < N_TOK * DIM) {
        void* p = nullptr;
        cudaGetSymbolAddress(&p, g_sae_scratch);
        sae = (float*)p;
    }
    float* fvu_ptr = outf + (out_size > 0 ? out_size - 1 : 0);

    static bool attr_set = false;
    if (!attr_set) {
        cudaFuncSetAttribute(skip_gemm_kernel,
                             cudaFuncAttributeMaxDynamicSharedMemorySize,
                             GEMM_SMEM_BYTES);
        attr_set = true;
    }

    zero_kernel<<<2, 512>>>();
    ystats_kernel<<<dim3(DIM / 256, 64), 256>>>(y);
    skip_gemm_kernel<<<dim3(DIM / GN, N_TOK / GM), 256, GEMM_SMEM_BYTES>>>(x, Wskip, sae);
    decode_kernel<<<N_TOK, 256>>>(la, li, Wdec, bdec, penc, pscale, y, sae);
    finalize_kernel<<<1, 1024>>>(fvu_ptr);
}

// round 5
// speedup vs baseline: 1.4191x; 1.3029x over previous
#include <cuda_runtime.h>
#include <cuda_bf16.h>
#include <mma.h>

using namespace nvcuda;

#define N_TOK 4096
#define TOPK  64
#define DIM   1024
#define NLAT  16384

// ---------------- device scratch (statically allocated; no runtime allocs) ----
__device__ float g_colsum[DIM];
__device__ float g_sumy2;
__device__ float g_err2;
__device__ float g_dec_scratch[N_TOK * DIM];   // decode partial sums
__device__ float g_sae_scratch[N_TOK * DIM];   // fallback if d_out too small

// ---------------- kernel 0: zero the reduction scratch ----------------------
__global__ void zero_kernel() {
    int t = blockIdx.x * blockDim.x + threadIdx.x;
    if (t < DIM) g_colsum[t] = 0.0f;
    if (t == 0) { g_sumy2 = 0.0f; g_err2 = 0.0f; }
}

// ---------------- kernel 1: y column sums + sum(y^2) -------------------------
__global__ __launch_bounds__(256) void ystats_kernel(const float* __restrict__ y) {
    int c  = blockIdx.x * 256 + threadIdx.x;
    int r0 = blockIdx.y * 64;
    float s = 0.0f, s2 = 0.0f;
#pragma unroll 4
    for (int r = 0; r < 64; r++) {
        float v = y[(r0 + r) * DIM + c];
        s += v;
        s2 += v * v;
    }
    atomicAdd(&g_colsum[c], s);
    __shared__ float red[256];
    red[threadIdx.x] = s2;
    __syncthreads();
    for (int off = 128; off > 0; off >>= 1) {
        if (threadIdx.x < off) red[threadIdx.x] += red[threadIdx.x + off];
        __syncthreads();
    }
    if (threadIdx.x == 0) atomicAdd(&g_sumy2, red[0]);
}

// ---------------- kernel 2: skip GEMM  out = x @ W_skip^T (tf32 wmma) --------
// 128x128 CTA tile, BK=32, cp.async double-buffered.  (round-3 proven version)
#define GM 128
#define GN 128
#define GK 32
#define GLD 36
#define ABUF (GM * GLD)
#define BBUF (GN * GLD)
#define GEMM_SMEM_BYTES ((2 * ABUF + 2 * BBUF) * 4)

__device__ __forceinline__ void cpa16(void* s, const void* g) {
    unsigned sa = (unsigned)__cvta_generic_to_shared(s);
    asm volatile("cp.async.cg.shared.global [%0], [%1], 16;" :: "r"(sa), "l"(g));
}

__global__ __launch_bounds__(256) void skip_gemm_kernel(
    const float* __restrict__ x, const float* __restrict__ Wskip,
    float* __restrict__ out)
{
    extern __shared__ float sm[];
    float* As = sm;
    float* Bs = sm + 2 * ABUF;

    const int m0 = blockIdx.y * GM;
    const int n0 = blockIdx.x * GN;
    const int tid = threadIdx.x;
    const int warp = tid >> 5;
    const int wm = warp & 3;
    const int wn = warp >> 2;

    wmma::fragment<wmma::accumulator, 16, 16, 8, float> c[2][4];
#pragma unroll
    for (int i = 0; i < 2; i++)
#pragma unroll
        for (int j = 0; j < 4; j++) wmma::fill_fragment(c[i][j], 0.0f);

    const int lrow = tid >> 3;
    const int lkg  = (tid & 7) * 4;

    auto issue = [&](int kt, int buf) {
        const int k0 = kt * GK;
        float* a = As + buf * ABUF;
        float* b = Bs + buf * BBUF;
#pragma unroll
        for (int i = 0; i < 4; i++) {
            int row = lrow + i * 32;
            cpa16(&a[row * GLD + lkg], &x[(size_t)(m0 + row) * DIM + k0 + lkg]);
        }
#pragma unroll
        for (int i = 0; i < 4; i++) {
            int row = lrow + i * 32;
            cpa16(&b[row * GLD + lkg], &Wskip[(size_t)(n0 + row) * DIM + k0 + lkg]);
        }
        asm volatile("cp.async.commit_group;");
    };

    const int NT = DIM / GK;
    issue(0, 0);

    for (int kt = 0; kt < NT; kt++) {
        const int buf = kt & 1;
        if (kt + 1 < NT) {
            issue(kt + 1, buf ^ 1);
            asm volatile("cp.async.wait_group 1;");
        } else {
            asm volatile("cp.async.wait_group 0;");
        }
        __syncthreads();

        const float* a_base = As + buf * ABUF + (wm * 32) * GLD;
        const float* b_base = Bs + buf * BBUF + (wn * 64) * GLD;
#pragma unroll
        for (int kk = 0; kk < 4; kk++) {
            wmma::fragment<wmma::matrix_a, 16, 16, 8, wmma::precision::tf32, wmma::row_major> af[2];
            wmma::fragment<wmma::matrix_b, 16, 16, 8, wmma::precision::tf32, wmma::col_major> bf[4];
#pragma unroll
            for (int i = 0; i < 2; i++) {
                wmma::load_matrix_sync(af[i], a_base + (i * 16) * GLD + kk * 8, GLD);
#pragma unroll
                for (int t = 0; t < af[i].num_elements; t++)
                    af[i].x[t] = wmma::__float_to_tf32(af[i].x[t]);
            }
#pragma unroll
            for (int j = 0; j < 4; j++) {
                wmma::load_matrix_sync(bf[j], b_base + (j * 16) * GLD + kk * 8, GLD);
#pragma unroll
                for (int t = 0; t < bf[j].num_elements; t++)
                    bf[j].x[t] = wmma::__float_to_tf32(bf[j].x[t]);
            }
#pragma unroll
            for (int i = 0; i < 2; i++)
#pragma unroll
                for (int j = 0; j < 4; j++)
                    wmma::mma_sync(c[i][j], af[i], bf[j], c[i][j]);
        }
        __syncthreads();
    }

#pragma unroll
    for (int i = 0; i < 2; i++)
#pragma unroll
        for (int j = 0; j < 4; j++) {
            int row = m0 + wm * 32 + i * 16;
            int col = n0 + wn * 64 + j * 16;
            wmma::store_matrix_sync(&out[(size_t)row * DIM + col], c[i][j], DIM,
                                    wmma::mem_row_major);
        }
}

// ---------------- kernel 3: decode partial (independent of GEMM) -------------
// dec[n][d] = b_dec[d] + sum_k acts[n][k] * W_dec[idx[n][k]][d]
__global__ __launch_bounds__(256) void decode_partial_kernel(
    const float* __restrict__ la, const int* __restrict__ li,
    const float* __restrict__ Wdec, const float* __restrict__ bdec,
    const float* __restrict__ penc, const float* __restrict__ pscale)
{
    const int n = blockIdx.x;
    const int t = threadIdx.x;
    __shared__ int   s_idx[TOPK];
    __shared__ float s_act[TOPK];
    if (t < TOPK) {
        int l = li[n * TOPK + t];
        s_idx[t] = l;
        s_act[t] = (la[n * TOPK + t] + penc[l]) * pscale[l];
    }
    __syncthreads();

    const int c = t * 4;
    float4 acc = *(const float4*)&bdec[c];

#pragma unroll 4
    for (int k = 0; k < TOPK; k++) {
        const float a = s_act[k];
        const float4 w = *(const float4*)&Wdec[(size_t)s_idx[k] * DIM + c];
        acc.x += a * w.x; acc.y += a * w.y; acc.z += a * w.z; acc.w += a * w.w;
    }
    *(float4*)&g_dec_scratch[(size_t)n * DIM + c] = acc;
}

// ---------------- kernel 4: combine gemm + decode, e^2 reduce ----------------
__global__ __launch_bounds__(256) void combine_kernel(
    const float* __restrict__ y, float* __restrict__ out)
{
    const int n = blockIdx.x;
    const int t = threadIdx.x;
    const int c = t * 4;
    const size_t base = (size_t)n * DIM + c;

    float4 g = *(const float4*)&out[base];
    const float4 d = *(const float4*)&g_dec_scratch[base];
    g.x += d.x; g.y += d.y; g.z += d.z; g.w += d.w;

    const float4 yv = *(const float4*)&y[base];
    float ex = yv.x - g.x, ey = yv.y - g.y, ez = yv.z - g.z, ew = yv.w - g.w;
    float e2 = ex * ex + ey * ey + ez * ez + ew * ew;
    *(float4*)&out[base] = g;

#pragma unroll
    for (int off = 16; off > 0; off >>= 1)
        e2 += __shfl_xor_sync(0xffffffffu, e2, off);
    __shared__ float wred[8];
    if ((t & 31) == 0) wred[t >> 5] = e2;
    __syncthreads();
    if (t < 8) {
        float v = wred[t];
#pragma unroll
        for (int off = 4; off > 0; off >>= 1)
            v += __shfl_xor_sync(0x000000ffu, v, off);
        if (t == 0) atomicAdd(&g_err2, v);
    }
}

// ---------------- kernel 5: finalize fvu -------------------------------------
__global__ void finalize_kernel(float* __restrict__ fvu_out) {
    __shared__ float red[1024];
    float s = g_colsum[threadIdx.x];
    red[threadIdx.x] = s * s;
    __syncthreads();
    for (int off = 512; off > 0; off >>= 1) {
        if (threadIdx.x < off) red[threadIdx.x] += red[threadIdx.x + off];
        __syncthreads();
    }
    if (threadIdx.x == 0) {
        float tv = g_sumy2 - red[0] / (float)N_TOK;
        *fvu_out = g_err2 / tv;
    }
}

// ---------------- launcher: graph-forked parallel branches -------------------
extern "C" void kernel_launch(void* const* d_in, const int* in_sizes, int n_in,
                              void* d_out, int out_size)
{
    const float* x      = (const float*)d_in[0];
    const float* y      = (const float*)d_in[1];
    const float* la     = (const float*)d_in[2];
    const int*   li     = (const int*)  d_in[3];
    const float* Wdec   = (const float*)d_in[4];
    const float* bdec   = (const float*)d_in[5];
    const float* penc   = (const float*)d_in[6];
    const float* pscale = (const float*)d_in[7];
    const float* Wskip  = (const float*)d_in[8];

    float* outf = (float*)d_out;
    float* sae = outf;
    if (out_size < N_TOK * DIM) {
        void* p = nullptr;
        cudaGetSymbolAddress(&p, g_sae_scratch);
        sae = (float*)p;
    }
    float* fvu_ptr = outf + (out_size > 0 ? out_size - 1 : 0);

    cudaFuncSetAttribute(skip_gemm_kernel,
                         cudaFuncAttributeMaxDynamicSharedMemorySize,
                         GEMM_SMEM_BYTES);

    // one-time side streams + events (created on the uncaptured correctness
    // call; reused inside capture where they become graph fork/join edges)
    static cudaStream_t s1 = nullptr, s2 = nullptr;
    static cudaEvent_t evFork = nullptr, evJ1 = nullptr, evJ2 = nullptr;
    if (!s1) {
        cudaStreamCreateWithFlags(&s1, cudaStreamNonBlocking);
        cudaStreamCreateWithFlags(&s2, cudaStreamNonBlocking);
        cudaEventCreateWithFlags(&evFork, cudaEventDisableTiming);
        cudaEventCreateWithFlags(&evJ1, cudaEventDisableTiming);
        cudaEventCreateWithFlags(&evJ2, cudaEventDisableTiming);
    }

    zero_kernel<<<2, 512>>>();

    cudaEventRecord(evFork, 0);
    cudaStreamWaitEvent(s1, evFork, 0);
    cudaStreamWaitEvent(s2, evFork, 0);

    // branch A (main stream): the long tensor-bound GEMM
    skip_gemm_kernel<<<dim3(DIM / GN, N_TOK / GM), 256, GEMM_SMEM_BYTES>>>(x, Wskip, sae);
    // branch B: y statistics
    ystats_kernel<<<dim3(DIM / 256, 64), 256, 0, s1>>>(y);
    // branch C: L2-bound decode gather (independent of GEMM)
    decode_partial_kernel<<<N_TOK, 256, 0, s2>>>(la, li, Wdec, bdec, penc, pscale);

    cudaEventRecord(evJ1, s1);
    cudaEventRecord(evJ2, s2);
    cudaStreamWaitEvent(0, evJ1, 0);
    cudaStreamWaitEvent(0, evJ2, 0);

    combine_kernel<<<N_TOK, 256>>>(y, sae);
    finalize_kernel<<<1, 1024>>>(fvu_ptr);
}

// round 6
// speedup vs baseline: 2.2022x; 1.5518x over previous
#include <cuda_runtime.h>
#include <cuda_fp16.h>
#include <mma.h>

using namespace nvcuda;

#define N_TOK 4096
#define TOPK  64
#define DIM   1024
#define NLAT  16384

// ---------------- device scratch (statically allocated; no runtime allocs) ----
__device__ float g_colsum[DIM];
__device__ float g_sumy2;
__device__ float g_err2;
__device__ float g_dec_scratch[N_TOK * DIM];   // decode partial sums
__device__ float g_sae_scratch[N_TOK * DIM];   // fallback if d_out too small
__device__ __half g_xh[N_TOK * DIM];           // fp16 copy of x
__device__ __half g_wh[DIM * DIM];             // fp16 copy of W_skip

// ---------------- kernel 0: zero the reduction scratch ----------------------
__global__ void zero_kernel() {
    int t = blockIdx.x * blockDim.x + threadIdx.x;
    if (t < DIM) g_colsum[t] = 0.0f;
    if (t == 0) { g_sumy2 = 0.0f; g_err2 = 0.0f; }
}

// ---------------- convert fp32 -> fp16 ---------------------------------------
__global__ __launch_bounds__(256) void convert_kernel(
    const float* __restrict__ src, __half* __restrict__ dst)
{
    int i = blockIdx.x * blockDim.x + threadIdx.x;   // one float4 per thread
    float4 v = *(const float4*)&src[(size_t)i * 4];
    __half2 h0 = __floats2half2_rn(v.x, v.y);
    __half2 h1 = __floats2half2_rn(v.z, v.w);
    uint2 u;
    u.x = reinterpret_cast<const unsigned&>(h0);
    u.y = reinterpret_cast<const unsigned&>(h1);
    *(uint2*)&dst[(size_t)i * 4] = u;
}

// ---------------- kernel 1: y column sums + sum(y^2) -------------------------
__global__ __launch_bounds__(256) void ystats_kernel(const float* __restrict__ y) {
    int c  = blockIdx.x * 256 + threadIdx.x;
    int r0 = blockIdx.y * 64;
    float s = 0.0f, s2 = 0.0f;
#pragma unroll 4
    for (int r = 0; r < 64; r++) {
        float v = y[(r0 + r) * DIM + c];
        s += v;
        s2 += v * v;
    }
    atomicAdd(&g_colsum[c], s);
    __shared__ float red[256];
    red[threadIdx.x] = s2;
    __syncthreads();
    for (int off = 128; off > 0; off >>= 1) {
        if (threadIdx.x < off) red[threadIdx.x] += red[threadIdx.x + off];
        __syncthreads();
    }
    if (threadIdx.x == 0) atomicAdd(&g_sumy2, red[0]);
}

// ---------------- kernel 2: skip GEMM  out = x @ W_skip^T (fp16 wmma) --------
// 128x128 CTA tile, BK=64 halves (128B rows), cp.async double-buffered.
#define HM 128
#define HN 128
#define HK 64
#define HLD 72                        // padded row length in halves (144B)
#define HABUF (HM * HLD)              // one A buffer (halves)
#define HBBUF (HN * HLD)
#define GEMM_SMEM_BYTES ((2 * HABUF + 2 * HBBUF) * 2)

__device__ __forceinline__ void cpa16(void* s, const void* g) {
    unsigned sa = (unsigned)__cvta_generic_to_shared(s);
    asm volatile("cp.async.cg.shared.global [%0], [%1], 16;" :: "r"(sa), "l"(g));
}

__global__ __launch_bounds__(256) void skip_gemm_kernel(
    const __half* __restrict__ xh, const __half* __restrict__ wh,
    float* __restrict__ out)
{
    extern __shared__ __half sm[];
    __half* As = sm;
    __half* Bs = sm + 2 * HABUF;

    const int m0 = blockIdx.y * HM;
    const int n0 = blockIdx.x * HN;
    const int tid = threadIdx.x;
    const int warp = tid >> 5;
    const int wm = warp & 3;      // 4 warp-rows of 32
    const int wn = warp >> 2;     // 2 warp-cols of 64

    wmma::fragment<wmma::accumulator, 16, 16, 16, float> c[2][4];
#pragma unroll
    for (int i = 0; i < 2; i++)
#pragma unroll
        for (int j = 0; j < 4; j++) wmma::fill_fragment(c[i][j], 0.0f);

    // tile fill: 128 rows x 8 segs(16B=8 halves) = 1024 tasks / 256 thr = 4 each
    const int lrow = tid >> 3;          // 0..31
    const int lseg = (tid & 7) * 8;     // half offset within row: 0..56

    auto issue = [&](int kt, int buf) {
        const int k0 = kt * HK;
        __half* a = As + buf * HABUF;
        __half* b = Bs + buf * HBBUF;
#pragma unroll
        for (int i = 0; i < 4; i++) {
            int row = lrow + i * 32;
            cpa16(&a[row * HLD + lseg], &xh[(size_t)(m0 + row) * DIM + k0 + lseg]);
        }
#pragma unroll
        for (int i = 0; i < 4; i++) {
            int row = lrow + i * 32;
            cpa16(&b[row * HLD + lseg], &wh[(size_t)(n0 + row) * DIM + k0 + lseg]);
        }
        asm volatile("cp.async.commit_group;");
    };

    const int NT = DIM / HK;   // 16
    issue(0, 0);

    for (int kt = 0; kt < NT; kt++) {
        const int buf = kt & 1;
        if (kt + 1 < NT) {
            issue(kt + 1, buf ^ 1);
            asm volatile("cp.async.wait_group 1;");
        } else {
            asm volatile("cp.async.wait_group 0;");
        }
        __syncthreads();

        const __half* a_base = As + buf * HABUF + (wm * 32) * HLD;
        const __half* b_base = Bs + buf * HBBUF + (wn * 64) * HLD;
#pragma unroll
        for (int kk = 0; kk < 4; kk++) {     // 4 x k16 = 64
            wmma::fragment<wmma::matrix_a, 16, 16, 16, __half, wmma::row_major> af[2];
            wmma::fragment<wmma::matrix_b, 16, 16, 16, __half, wmma::col_major> bf[4];
#pragma unroll
            for (int i = 0; i < 2; i++)
                wmma::load_matrix_sync(af[i], a_base + (i * 16) * HLD + kk * 16, HLD);
#pragma unroll
            for (int j = 0; j < 4; j++)
                wmma::load_matrix_sync(bf[j], b_base + (j * 16) * HLD + kk * 16, HLD);
#pragma unroll
            for (int i = 0; i < 2; i++)
#pragma unroll
                for (int j = 0; j < 4; j++)
                    wmma::mma_sync(c[i][j], af[i], bf[j], c[i][j]);
        }
        __syncthreads();
    }

#pragma unroll
    for (int i = 0; i < 2; i++)
#pragma unroll
        for (int j = 0; j < 4; j++) {
            int row = m0 + wm * 32 + i * 16;
            int col = n0 + wn * 64 + j * 16;
            wmma::store_matrix_sync(&out[(size_t)row * DIM + col], c[i][j], DIM,
                                    wmma::mem_row_major);
        }
}

// ---------------- kernel 3: decode partial (independent of GEMM) -------------
__global__ __launch_bounds__(256) void decode_partial_kernel(
    const float* __restrict__ la, const int* __restrict__ li,
    const float* __restrict__ Wdec, const float* __restrict__ bdec,
    const float* __restrict__ penc, const float* __restrict__ pscale)
{
    const int n = blockIdx.x;
    const int t = threadIdx.x;
    __shared__ int   s_idx[TOPK];
    __shared__ float s_act[TOPK];
    if (t < TOPK) {
        int l = li[n * TOPK + t];
        s_idx[t] = l;
        s_act[t] = (la[n * TOPK + t] + penc[l]) * pscale[l];
    }
    __syncthreads();

    const int c = t * 4;
    float4 acc = *(const float4*)&bdec[c];

#pragma unroll 4
    for (int k = 0; k < TOPK; k++) {
        const float a = s_act[k];
        const float4 w = *(const float4*)&Wdec[(size_t)s_idx[k] * DIM + c];
        acc.x += a * w.x; acc.y += a * w.y; acc.z += a * w.z; acc.w += a * w.w;
    }
    *(float4*)&g_dec_scratch[(size_t)n * DIM + c] = acc;
}

// ---------------- kernel 4: combine gemm + decode, e^2 reduce ----------------
__global__ __launch_bounds__(256) void combine_kernel(
    const float* __restrict__ y, float* __restrict__ out)
{
    const int n = blockIdx.x;
    const int t = threadIdx.x;
    const int c = t * 4;
    const size_t base = (size_t)n * DIM + c;

    float4 g = *(const float4*)&out[base];
    const float4 d = *(const float4*)&g_dec_scratch[base];
    g.x += d.x; g.y += d.y; g.z += d.z; g.w += d.w;

    const float4 yv = *(const float4*)&y[base];
    float ex = yv.x - g.x, ey = yv.y - g.y, ez = yv.z - g.z, ew = yv.w - g.w;
    float e2 = ex * ex + ey * ey + ez * ez + ew * ew;
    *(float4*)&out[base] = g;

#pragma unroll
    for (int off = 16; off > 0; off >>= 1)
        e2 += __shfl_xor_sync(0xffffffffu, e2, off);
    __shared__ float wred[8];
    if ((t & 31) == 0) wred[t >> 5] = e2;
    __syncthreads();
    if (t < 8) {
        float v = wred[t];
#pragma unroll
        for (int off = 4; off > 0; off >>= 1)
            v += __shfl_xor_sync(0x000000ffu, v, off);
        if (t == 0) atomicAdd(&g_err2, v);
    }
}

// ---------------- kernel 5: finalize fvu -------------------------------------
__global__ void finalize_kernel(float* __restrict__ fvu_out) {
    __shared__ float red[1024];
    float s = g_colsum[threadIdx.x];
    red[threadIdx.x] = s * s;
    __syncthreads();
    for (int off = 512; off > 0; off >>= 1) {
        if (threadIdx.x < off) red[threadIdx.x] += red[threadIdx.x + off];
        __syncthreads();
    }
    if (threadIdx.x == 0) {
        float tv = g_sumy2 - red[0] / (float)N_TOK;
        *fvu_out = g_err2 / tv;
    }
}

// ---------------- launcher: graph-forked parallel branches -------------------
extern "C" void kernel_launch(void* const* d_in, const int* in_sizes, int n_in,
                              void* d_out, int out_size)
{
    const float* x      = (const float*)d_in[0];
    const float* y      = (const float*)d_in[1];
    const float* la     = (const float*)d_in[2];
    const int*   li     = (const int*)  d_in[3];
    const float* Wdec   = (const float*)d_in[4];
    const float* bdec   = (const float*)d_in[5];
    const float* penc   = (const float*)d_in[6];
    const float* pscale = (const float*)d_in[7];
    const float* Wskip  = (const float*)d_in[8];

    float* outf = (float*)d_out;
    float* sae = outf;
    if (out_size < N_TOK * DIM) {
        void* p = nullptr;
        cudaGetSymbolAddress(&p, g_sae_scratch);
        sae = (float*)p;
    }
    float* fvu_ptr = outf + (out_size > 0 ? out_size - 1 : 0);

    __half* xh = nullptr; __half* wh = nullptr;
    {
        void* p = nullptr;
        cudaGetSymbolAddress(&p, g_xh); xh = (__half*)p;
        cudaGetSymbolAddress(&p, g_wh); wh = (__half*)p;
    }

    cudaFuncSetAttribute(skip_gemm_kernel,
                         cudaFuncAttributeMaxDynamicSharedMemorySize,
                         GEMM_SMEM_BYTES);

    static cudaStream_t s1 = nullptr, s2 = nullptr;
    static cudaEvent_t evFork = nullptr, evJ1 = nullptr, evJ2 = nullptr;
    if (!s1) {
        cudaStreamCreateWithFlags(&s1, cudaStreamNonBlocking);
        cudaStreamCreateWithFlags(&s2, cudaStreamNonBlocking);
        cudaEventCreateWithFlags(&evFork, cudaEventDisableTiming);
        cudaEventCreateWithFlags(&evJ1, cudaEventDisableTiming);
        cudaEventCreateWithFlags(&evJ2, cudaEventDisableTiming);
    }

    zero_kernel<<<2, 512>>>();

    cudaEventRecord(evFork, 0);
    cudaStreamWaitEvent(s1, evFork, 0);
    cudaStreamWaitEvent(s2, evFork, 0);

    // branch A (main stream): fp16 convert + tensor GEMM
    convert_kernel<<<(N_TOK * DIM / 4) / 256, 256>>>(x, xh);
    convert_kernel<<<(DIM * DIM / 4) / 256, 256>>>(Wskip, wh);
    skip_gemm_kernel<<<dim3(DIM / HN, N_TOK / HM), 256, GEMM_SMEM_BYTES>>>(xh, wh, sae);
    // branch B: y statistics
    ystats_kernel<<<dim3(DIM / 256, 64), 256, 0, s1>>>(y);
    // branch C: L2-bound decode gather (independent of GEMM)
    decode_partial_kernel<<<N_TOK, 256, 0, s2>>>(la, li, Wdec, bdec, penc, pscale);

    cudaEventRecord(evJ1, s1);
    cudaEventRecord(evJ2, s2);
    cudaStreamWaitEvent(0, evJ1, 0);
    cudaStreamWaitEvent(0, evJ2, 0);

    combine_kernel<<<N_TOK, 256>>>(y, sae);
    finalize_kernel<<<1, 1024>>>(fvu_ptr);
}

// round 7
// speedup vs baseline: 2.4277x; 1.1024x over previous
#include <cuda_runtime.h>
#include <cuda_fp16.h>
#include <cuda_bf16.h>
#include <mma.h>
#include <cstdint>

using namespace nvcuda;

#define N_TOK 4096
#define TOPK  64
#define DIM   1024
#define NLAT  16384

// ---------------- device scratch (statically allocated; no runtime allocs) ----
__device__ float g_colsum[DIM];
__device__ float g_sumy2;
__device__ float g_err2;
__device__ float g_dec_scratch[N_TOK * DIM];        // decode partial sums
__device__ float g_sae_scratch[N_TOK * DIM];        // fallback if d_out too small
__device__ __half g_xh[N_TOK * DIM];                // fp16 copy of x
__device__ __half g_wh[DIM * DIM];                  // fp16 copy of W_skip
__device__ __nv_bfloat16 g_wdec_bf[NLAT * DIM];     // bf16 copy of W_dec

// ---------------- kernel 0: zero the reduction scratch ----------------------
__global__ void zero_kernel() {
    int t = blockIdx.x * blockDim.x + threadIdx.x;
    if (t < DIM) g_colsum[t] = 0.0f;
    if (t == 0) { g_sumy2 = 0.0f; g_err2 = 0.0f; }
}

// ---------------- convert fp32 -> fp16 ---------------------------------------
__global__ __launch_bounds__(256) void convert_h_kernel(
    const float* __restrict__ src, __half* __restrict__ dst)
{
    int i = blockIdx.x * blockDim.x + threadIdx.x;   // one float4 per thread
    float4 v = *(const float4*)&src[(size_t)i * 4];
    __half2 h0 = __floats2half2_rn(v.x, v.y);
    __half2 h1 = __floats2half2_rn(v.z, v.w);
    uint2 u;
    u.x = reinterpret_cast<const unsigned&>(h0);
    u.y = reinterpret_cast<const unsigned&>(h1);
    *(uint2*)&dst[(size_t)i * 4] = u;
}

// ---------------- convert fp32 -> bf16 (8 elems/thread) ----------------------
__device__ __forceinline__ uint32_t pack_bf(float a, float b) {
    __nv_bfloat162 h = __floats2bfloat162_rn(a, b);  // .x=a(lo) .y=b(hi)
    return reinterpret_cast<const uint32_t&>(h);
}
__global__ __launch_bounds__(256) void convert_bf_kernel(
    const float* __restrict__ src, __nv_bfloat16* __restrict__ dst)
{
    size_t i = (size_t)(blockIdx.x * blockDim.x + threadIdx.x) * 8;
    float4 v0 = *(const float4*)&src[i];
    float4 v1 = *(const float4*)&src[i + 4];
    uint4 o;
    o.x = pack_bf(v0.x, v0.y);
    o.y = pack_bf(v0.z, v0.w);
    o.z = pack_bf(v1.x, v1.y);
    o.w = pack_bf(v1.z, v1.w);
    *(uint4*)&dst[i] = o;
}

// ---------------- kernel 1: y column sums + sum(y^2) -------------------------
__global__ __launch_bounds__(256) void ystats_kernel(const float* __restrict__ y) {
    int c  = blockIdx.x * 256 + threadIdx.x;
    int r0 = blockIdx.y * 64;
    float s = 0.0f, s2 = 0.0f;
#pragma unroll 4
    for (int r = 0; r < 64; r++) {
        float v = y[(r0 + r) * DIM + c];
        s += v;
        s2 += v * v;
    }
    atomicAdd(&g_colsum[c], s);
    __shared__ float red[256];
    red[threadIdx.x] = s2;
    __syncthreads();
    for (int off = 128; off > 0; off >>= 1) {
        if (threadIdx.x < off) red[threadIdx.x] += red[threadIdx.x + off];
        __syncthreads();
    }
    if (threadIdx.x == 0) atomicAdd(&g_sumy2, red[0]);
}

// ---------------- kernel 2: skip GEMM  out = x @ W_skip^T (fp16 wmma) --------
#define HM 128
#define HN 128
#define HK 64
#define HLD 72
#define HABUF (HM * HLD)
#define HBBUF (HN * HLD)
#define GEMM_SMEM_BYTES ((2 * HABUF + 2 * HBBUF) * 2)

__device__ __forceinline__ void cpa16(void* s, const void* g) {
    unsigned sa = (unsigned)__cvta_generic_to_shared(s);
    asm volatile("cp.async.cg.shared.global [%0], [%1], 16;" :: "r"(sa), "l"(g));
}

__global__ __launch_bounds__(256) void skip_gemm_kernel(
    const __half* __restrict__ xh, const __half* __restrict__ wh,
    float* __restrict__ out)
{
    extern __shared__ __half sm[];
    __half* As = sm;
    __half* Bs = sm + 2 * HABUF;

    const int m0 = blockIdx.y * HM;
    const int n0 = blockIdx.x * HN;
    const int tid = threadIdx.x;
    const int warp = tid >> 5;
    const int wm = warp & 3;
    const int wn = warp >> 2;

    wmma::fragment<wmma::accumulator, 16, 16, 16, float> c[2][4];
#pragma unroll
    for (int i = 0; i < 2; i++)
#pragma unroll
        for (int j = 0; j < 4; j++) wmma::fill_fragment(c[i][j], 0.0f);

    const int lrow = tid >> 3;
    const int lseg = (tid & 7) * 8;

    auto issue = [&](int kt, int buf) {
        const int k0 = kt * HK;
        __half* a = As + buf * HABUF;
        __half* b = Bs + buf * HBBUF;
#pragma unroll
        for (int i = 0; i < 4; i++) {
            int row = lrow + i * 32;
            cpa16(&a[row * HLD + lseg], &xh[(size_t)(m0 + row) * DIM + k0 + lseg]);
        }
#pragma unroll
        for (int i = 0; i < 4; i++) {
            int row = lrow + i * 32;
            cpa16(&b[row * HLD + lseg], &wh[(size_t)(n0 + row) * DIM + k0 + lseg]);
        }
        asm volatile("cp.async.commit_group;");
    };

    const int NT = DIM / HK;
    issue(0, 0);

    for (int kt = 0; kt < NT; kt++) {
        const int buf = kt & 1;
        if (kt + 1 < NT) {
            issue(kt + 1, buf ^ 1);
            asm volatile("cp.async.wait_group 1;");
        } else {
            asm volatile("cp.async.wait_group 0;");
        }
        __syncthreads();

        const __half* a_base = As + buf * HABUF + (wm * 32) * HLD;
        const __half* b_base = Bs + buf * HBBUF + (wn * 64) * HLD;
#pragma unroll
        for (int kk = 0; kk < 4; kk++) {
            wmma::fragment<wmma::matrix_a, 16, 16, 16, __half, wmma::row_major> af[2];
            wmma::fragment<wmma::matrix_b, 16, 16, 16, __half, wmma::col_major> bf[4];
#pragma unroll
            for (int i = 0; i < 2; i++)
                wmma::load_matrix_sync(af[i], a_base + (i * 16) * HLD + kk * 16, HLD);
#pragma unroll
            for (int j = 0; j < 4; j++)
                wmma::load_matrix_sync(bf[j], b_base + (j * 16) * HLD + kk * 16, HLD);
#pragma unroll
            for (int i = 0; i < 2; i++)
#pragma unroll
                for (int j = 0; j < 4; j++)
                    wmma::mma_sync(c[i][j], af[i], bf[j], c[i][j]);
        }
        __syncthreads();
    }

#pragma unroll
    for (int i = 0; i < 2; i++)
#pragma unroll
        for (int j = 0; j < 4; j++) {
            int row = m0 + wm * 32 + i * 16;
            int col = n0 + wn * 64 + j * 16;
            wmma::store_matrix_sync(&out[(size_t)row * DIM + col], c[i][j], DIM,
                                    wmma::mem_row_major);
        }
}

// ---------------- kernel 3: decode partial, bf16 gather ----------------------
// 128 threads/CTA, 8 cols/thread, one uint4 (8 bf16) load per (k, thread).
__device__ __forceinline__ float bf_lo(uint32_t u) { return __uint_as_float(u << 16); }
__device__ __forceinline__ float bf_hi(uint32_t u) { return __uint_as_float(u & 0xffff0000u); }

__global__ __launch_bounds__(128) void decode_partial_kernel(
    const float* __restrict__ la, const int* __restrict__ li,
    const __nv_bfloat16* __restrict__ Wdec, const float* __restrict__ bdec,
    const float* __restrict__ penc, const float* __restrict__ pscale)
{
    const int n = blockIdx.x;
    const int t = threadIdx.x;
    __shared__ int   s_idx[TOPK];
    __shared__ float s_act[TOPK];
    if (t < TOPK) {
        int l = li[n * TOPK + t];
        s_idx[t] = l;
        s_act[t] = (la[n * TOPK + t] + penc[l]) * pscale[l];
    }
    __syncthreads();

    const int c = t * 8;
    float acc[8];
    {
        float4 b0 = *(const float4*)&bdec[c];
        float4 b1 = *(const float4*)&bdec[c + 4];
        acc[0] = b0.x; acc[1] = b0.y; acc[2] = b0.z; acc[3] = b0.w;
        acc[4] = b1.x; acc[5] = b1.y; acc[6] = b1.z; acc[7] = b1.w;
    }

#pragma unroll 4
    for (int k = 0; k < TOPK; k++) {
        const float a = s_act[k];
        const uint4 w = *(const uint4*)&Wdec[(size_t)s_idx[k] * DIM + c];
        acc[0] += a * bf_lo(w.x); acc[1] += a * bf_hi(w.x);
        acc[2] += a * bf_lo(w.y); acc[3] += a * bf_hi(w.y);
        acc[4] += a * bf_lo(w.z); acc[5] += a * bf_hi(w.z);
        acc[6] += a * bf_lo(w.w); acc[7] += a * bf_hi(w.w);
    }

    float* o = &g_dec_scratch[(size_t)n * DIM + c];
    *(float4*)&o[0] = make_float4(acc[0], acc[1], acc[2], acc[3]);
    *(float4*)&o[4] = make_float4(acc[4], acc[5], acc[6], acc[7]);
}

// ---------------- kernel 4: combine gemm + decode, e^2 reduce ----------------
__global__ __launch_bounds__(256) void combine_kernel(
    const float* __restrict__ y, float* __restrict__ out)
{
    const int n = blockIdx.x;
    const int t = threadIdx.x;
    const int c = t * 4;
    const size_t base = (size_t)n * DIM + c;

    float4 g = *(const float4*)&out[base];
    const float4 d = *(const float4*)&g_dec_scratch[base];
    g.x += d.x; g.y += d.y; g.z += d.z; g.w += d.w;

    const float4 yv = *(const float4*)&y[base];
    float ex = yv.x - g.x, ey = yv.y - g.y, ez = yv.z - g.z, ew = yv.w - g.w;
    float e2 = ex * ex + ey * ey + ez * ez + ew * ew;
    *(float4*)&out[base] = g;

#pragma unroll
    for (int off = 16; off > 0; off >>= 1)
        e2 += __shfl_xor_sync(0xffffffffu, e2, off);
    __shared__ float wred[8];
    if ((t & 31) == 0) wred[t >> 5] = e2;
    __syncthreads();
    if (t < 8) {
        float v = wred[t];
#pragma unroll
        for (int off = 4; off > 0; off >>= 1)
            v += __shfl_xor_sync(0x000000ffu, v, off);
        if (t == 0) atomicAdd(&g_err2, v);
    }
}

// ---------------- kernel 5: finalize fvu -------------------------------------
__global__ void finalize_kernel(float* __restrict__ fvu_out) {
    __shared__ float red[1024];
    float s = g_colsum[threadIdx.x];
    red[threadIdx.x] = s * s;
    __syncthreads();
    for (int off = 512; off > 0; off >>= 1) {
        if (threadIdx.x < off) red[threadIdx.x] += red[threadIdx.x + off];
        __syncthreads();
    }
    if (threadIdx.x == 0) {
        float tv = g_sumy2 - red[0] / (float)N_TOK;
        *fvu_out = g_err2 / tv;
    }
}

// ---------------- launcher: graph-forked parallel branches -------------------
extern "C" void kernel_launch(void* const* d_in, const int* in_sizes, int n_in,
                              void* d_out, int out_size)
{
    const float* x      = (const float*)d_in[0];
    const float* y      = (const float*)d_in[1];
    const float* la     = (const float*)d_in[2];
    const int*   li     = (const int*)  d_in[3];
    const float* Wdec   = (const float*)d_in[4];
    const float* bdec   = (const float*)d_in[5];
    const float* penc   = (const float*)d_in[6];
    const float* pscale = (const float*)d_in[7];
    const float* Wskip  = (const float*)d_in[8];

    float* outf = (float*)d_out;
    float* sae = outf;
    if (out_size < N_TOK * DIM) {
        void* p = nullptr;
        cudaGetSymbolAddress(&p, g_sae_scratch);
        sae = (float*)p;
    }
    float* fvu_ptr = outf + (out_size > 0 ? out_size - 1 : 0);

    __half* xh = nullptr; __half* wh = nullptr; __nv_bfloat16* wdec_bf = nullptr;
    {
        void* p = nullptr;
        cudaGetSymbolAddress(&p, g_xh); xh = (__half*)p;
        cudaGetSymbolAddress(&p, g_wh); wh = (__half*)p;
        cudaGetSymbolAddress(&p, g_wdec_bf); wdec_bf = (__nv_bfloat16*)p;
    }

    cudaFuncSetAttribute(skip_gemm_kernel,
                         cudaFuncAttributeMaxDynamicSharedMemorySize,
                         GEMM_SMEM_BYTES);

    static cudaStream_t s1 = nullptr, s2 = nullptr;
    static cudaEvent_t evFork = nullptr, evJ1 = nullptr, evJ2 = nullptr;
    if (!s1) {
        cudaStreamCreateWithFlags(&s1, cudaStreamNonBlocking);
        cudaStreamCreateWithFlags(&s2, cudaStreamNonBlocking);
        cudaEventCreateWithFlags(&evFork, cudaEventDisableTiming);
        cudaEventCreateWithFlags(&evJ1, cudaEventDisableTiming);
        cudaEventCreateWithFlags(&evJ2, cudaEventDisableTiming);
    }

    zero_kernel<<<2, 512>>>();

    cudaEventRecord(evFork, 0);
    cudaStreamWaitEvent(s1, evFork, 0);
    cudaStreamWaitEvent(s2, evFork, 0);

    // branch A (main stream): fp16 converts + tensor GEMM
    convert_h_kernel<<<(N_TOK * DIM / 4) / 256, 256>>>(x, xh);
    convert_h_kernel<<<(DIM * DIM / 4) / 256, 256>>>(Wskip, wh);
    skip_gemm_kernel<<<dim3(DIM / HN, N_TOK / HM), 256, GEMM_SMEM_BYTES>>>(xh, wh, sae);
    // branch B: y statistics
    ystats_kernel<<<dim3(DIM / 256, 64), 256, 0, s1>>>(y);
    // branch C: bf16 convert of W_dec, then L2-bound decode gather
    convert_bf_kernel<<<(NLAT * DIM / 8) / 256, 256, 0, s2>>>(Wdec, wdec_bf);
    decode_partial_kernel<<<N_TOK, 128, 0, s2>>>(la, li, wdec_bf, bdec, penc, pscale);

    cudaEventRecord(evJ1, s1);
    cudaEventRecord(evJ2, s2);
    cudaStreamWaitEvent(0, evJ1, 0);
    cudaStreamWaitEvent(0, evJ2, 0);

    combine_kernel<<<N_TOK, 256>>>(y, sae);
    finalize_kernel<<<1, 1024>>>(fvu_ptr);
}